// round 15
// baseline (speedup 1.0000x reference)
#include <cuda_runtime.h>
#include <cstdint>
#include <cstddef>

#define BB 4096
#define TT 32
#define AA 4
#define OBSD 115
#define HH 64
#define KK 8
#define ACTN 19
#define FEATN 23
#define INDIM 99
#define NBLK 128
typedef unsigned long long u64;

__device__ float g_xall[(size_t)TT * BB * HH];
__device__ float g_gi[(size_t)TT * NBLK * 64 * 96];

__device__ __forceinline__ u64 ffma2(u64 a, u64 b, u64 c) {
    u64 d;
    asm("fma.rn.f32x2 %0, %1, %2, %3;" : "=l"(d) : "l"(a), "l"(b), "l"(c));
    return d;
}
__device__ __forceinline__ u64 pack2(float lo, float hi) {
    u64 d;
    asm("mov.b64 %0, {%1, %2};" : "=l"(d) : "f"(lo), "f"(hi));
    return d;
}
__device__ __forceinline__ float sumh(u64 v) {
    float lo = __uint_as_float((unsigned)(v & 0xffffffffull));
    float hi = __uint_as_float((unsigned)(v >> 32));
    return lo + hi;
}
__device__ __forceinline__ float sigf(float x) {
    return __fdividef(1.f, 1.f + __expf(-x));
}
__device__ __forceinline__ float tanhf_fast(float x) {
    return __fdividef(2.f, 1.f + __expf(-2.f * x)) - 1.f;
}

// ---------------- kernel 1: features + projection + LN + ReLU (R6, 62.7us) ----------------
#define KF_PT 0
#define KF_PAR 25344
#define KF_FB (25344 + 768)
#define KF_AB (KF_FB + 25600)
#define KF_SMEM (KF_AB + 4096)

__global__ __launch_bounds__(256) void k_feat(const float* __restrict__ obs,
                                              const int* __restrict__ act,
                                              const float* __restrict__ pW,
                                              const float* __restrict__ pb,
                                              const float* __restrict__ lg,
                                              const float* __restrict__ lb) {
    extern __shared__ char smc[];
    float2* pTp = (float2*)(smc + KF_PT);
    float2* sbp = (float2*)(smc + KF_PAR);
    float2* sgp = sbp + 32;
    float2* sbtp = sbp + 64;
    float* fbuf = (float*)(smc + KF_FB);
    int* abuf = (int*)(smc + KF_AB);

    int tid = threadIdx.x;
    for (int i = tid; i < INDIM * 32; i += 256) {
        int f = i >> 5, hp = i & 31;
        pTp[i] = make_float2(pW[(2 * hp) * INDIM + f], pW[(2 * hp + 1) * INDIM + f]);
    }
    if (tid < 32) {
        sbp[tid] = make_float2(pb[2 * tid], pb[2 * tid + 1]);
        sgp[tid] = make_float2(lg[2 * tid], lg[2 * tid + 1]);
        sbtp[tid] = make_float2(lb[2 * tid], lb[2 * tid + 1]);
    }
    {
        int task = blockIdx.x * 256 + tid;
        int b = task >> 5, t = task & 31;
        const float* o = obs + (size_t)(b * TT + t) * AA * OBSD;
        float px[AA], py[AA];
#pragma unroll
        for (int a = 0; a < AA; a++) { px[a] = o[a * OBSD]; py[a] = o[a * OBSD + 1]; }
        float bx = o[88], by = o[89];
        float bvx = 0.f, bvy = 0.f;
        if (t > 0) { bvx = bx - o[88 - AA * OBSD]; bvy = by - o[89 - AA * OBSD]; }
        float cx = 0.25f * (px[0] + px[1] + px[2] + px[3]);
        float cy = 0.25f * (py[0] + py[1] + py[2] + py[3]);
        float sp = 0.f;
#pragma unroll
        for (int a = 0; a < AA; a++) {
            float dx = px[a] - cx, dy = py[a] - cy;
            sp += dx * dx + dy * dy;
        }
        float spread = sqrtf(0.25f * sp + 1e-6f);
        float* fb = fbuf + tid * 25;
        fb[0] = bx; fb[1] = by; fb[2] = bvx; fb[3] = bvy;
#pragma unroll
        for (int a = 0; a < AA; a++) { fb[4 + 2 * a] = px[a]; fb[5 + 2 * a] = py[a]; }
        fb[12] = cx; fb[13] = cy; fb[14] = spread;
#pragma unroll
        for (int i = 0; i < AA; i++) {
            float best = 3.4e38f; int bj = 0;
#pragma unroll
            for (int j = 0; j < AA; j++) {
                if (j == i) continue;
                float dx = px[i] - px[j], dy = py[i] - py[j];
                float d = dx * dx + dy * dy;
                if (d < best) { best = d; bj = j; }
            }
            fb[15 + 2 * i] = px[bj] - px[i];
            fb[16 + 2 * i] = py[bj] - py[i];
        }
        const int* ap = act + (b * TT + t) * AA;
#pragma unroll
        for (int a = 0; a < AA; a++) abuf[tid * 4 + a] = FEATN + a * ACTN + ap[a];
    }
    __syncthreads();

    int lane = tid & 31, w = tid >> 5;
    const u64* pTq = (const u64*)pTp;
    u64 bini = *(const u64*)&sbp[lane];
    for (int tt = 0; tt < 32; tt++) {
        int s = w * 32 + tt;
        const float* fb = fbuf + s * 25;
        u64 acc = bini;
#pragma unroll
        for (int f = 0; f < FEATN; f++) {
            float x = fb[f];
            acc = ffma2(pack2(x, x), pTq[f * 32 + lane], acc);
        }
        u64 one2 = pack2(1.f, 1.f);
#pragma unroll
        for (int a = 0; a < AA; a++) {
            int col = abuf[s * 4 + a];
            acc = ffma2(one2, pTq[col * 32 + lane], acc);
        }
        float a0 = __uint_as_float((unsigned)(acc & 0xffffffffull));
        float a1 = __uint_as_float((unsigned)(acc >> 32));
        float sm = a0 + a1;
#pragma unroll
        for (int off = 16; off; off >>= 1) sm += __shfl_xor_sync(0xffffffffu, sm, off);
        float mu = sm * (1.f / 64.f);
        float d0 = a0 - mu, d1 = a1 - mu;
        float v = d0 * d0 + d1 * d1;
#pragma unroll
        for (int off = 16; off; off >>= 1) v += __shfl_xor_sync(0xffffffffu, v, off);
        float sc = rsqrtf(v * (1.f / 64.f) + 1e-5f);
        float2 g = sgp[lane], bt = sbtp[lane];
        float y0 = fmaxf(fmaf(d0 * sc, g.x, bt.x), 0.f);
        float y1 = fmaxf(fmaf(d1 * sc, g.y, bt.y), 0.f);
        int task = blockIdx.x * 256 + s;
        int b = task >> 5, t = task & 31;
        *(float2*)(g_xall + ((size_t)t * BB + b) * HH + 2 * lane) = make_float2(y0, y1);
    }
}

// ---------------- kernel 2: layer-0 input-gate GEMM (R14 one-wave, ~144us) ----------------
#define GI_XS 65536
#define GI_SBI (65536 + 16896)
#define GI_SMEM (GI_SBI + 768)
__global__ __launch_bounds__(512, 2) void k_gi0(const float* __restrict__ Wih0,
                                                const float* __restrict__ bih0) {
    extern __shared__ char smc[];
    float2* wq = (float2*)smc;
    float2* xs = (float2*)(smc + GI_XS);
    float* sbi = (float*)(smc + GI_SBI);

    int tid = threadIdx.x;
    for (int i = tid; i < 64 * 32 * 4; i += 512) {
        int j = i >> 7, kp = (i >> 2) & 31, m = i & 3;
        float2 v = make_float2(0.f, 0.f);
        if (m < 3) {
            const float* src = Wih0 + (size_t)(m * 64 + j) * 64 + 2 * kp;
            v.x = src[0]; v.y = src[1];
        }
        wq[i] = v;
    }
    if (tid < 192) sbi[tid] = bih0[tid];

    int r = tid & 31, w = tid >> 5, jbase = w * 4;
    int blk = blockIdx.x & 127, tchunk = blockIdx.x >> 7;
    int rowbase = blk * 32;
    int t0 = tchunk * 16;

    for (int i = tid; i < 1024; i += 512) {
        int rr = i >> 5, kp = i & 31;
        xs[kp * 33 + rr] =
            *((const float2*)(g_xall + ((size_t)t0 * BB + rowbase + rr) * HH) + kp);
    }
    __syncthreads();

    for (int tq = 0; tq < 16; tq++) {
        int t = t0 + tq;
        if (tq + 1 < 16) {
            for (int i = tid; i < 1024; i += 512) {
                int rr = i >> 5, kp = i & 31;
                xs[((tq + 1) & 1) * 1056 + kp * 33 + rr] =
                    *((const float2*)(g_xall + ((size_t)(t + 1) * BB + rowbase + rr) * HH) + kp);
            }
        }
        const float2* xsrc = xs + (tq & 1) * 1056;
        u64 acc[12];
#pragma unroll
        for (int i = 0; i < 12; i++) acc[i] = 0ull;
#pragma unroll
        for (int kp = 0; kp < 32; kp++) {
            u64 x2 = *(const u64*)&xsrc[kp * 33 + r];
#pragma unroll
            for (int j = 0; j < 4; j++) {
                const ulonglong2* wp = (const ulonglong2*)&wq[((jbase + j) * 32 + kp) * 4];
                ulonglong2 wa = wp[0];
                ulonglong2 wb = wp[1];
                acc[j * 3 + 0] = ffma2(x2, wa.x, acc[j * 3 + 0]);
                acc[j * 3 + 1] = ffma2(x2, wa.y, acc[j * 3 + 1]);
                acc[j * 3 + 2] = ffma2(x2, wb.x, acc[j * 3 + 2]);
            }
        }
        float* gout = g_gi + ((size_t)(t * NBLK + blk) * 64) * 96;
#pragma unroll
        for (int j = 0; j < 4; j++) {
            int jj = jbase + j;
#pragma unroll
            for (int m = 0; m < 3; m++)
                gout[jj * 96 + m * 32 + r] = sumh(acc[j * 3 + m]) + sbi[m * 64 + jj];
        }
        __syncthreads();
    }
}

// ========== kernel 3: GRU recurrence, crossbar-efficient lane remap ==========
// lane l: jl=l>>3 (one of warp's 4 j), rg=l&7 (row group); rows rg+8m, m=0..3.
// h layout: [kp][rg][m] u64 (kp = j-pair of h dims). Weight LDS per-lane distinct.
// smem: wrz0 33792 | wn0 16896 | wA/wB/wC 3x33792 | hb 32768 | bias 2048 = 186880
#define W_N0 33792
#define W_A1 (W_N0 + 16896)
#define W_B1 (W_A1 + 33792)
#define W_C1 (W_B1 + 33792)
#define SM_HB (W_C1 + 33792)
#define SM_BI0 (SM_HB + 32768)
#define SM_BI1 (SM_BI0 + 1024)
#define SMEM_TOTAL (SM_BI1 + 1024)

__global__ __launch_bounds__(512, 1) void k_gru(
    const float* __restrict__ Whh0, const float* __restrict__ bhh0,
    const float* __restrict__ Wih1, const float* __restrict__ Whh1,
    const float* __restrict__ bih1, const float* __restrict__ bhh1,
    const float* __restrict__ cW1, const float* __restrict__ cb1,
    const float* __restrict__ cW2, const float* __restrict__ cb2,
    float* __restrict__ out) {
    extern __shared__ char smc[];
    ulonglong2* wrz0 = (ulonglong2*)smc;             // [j*33+kp] {w_r, w_z} k-pairs
    u64* wn0 = (u64*)(smc + W_N0);                   // [j*33+kp] w_n
    ulonglong2* wA = (ulonglong2*)(smc + W_A1);      // {Wih1_r, Wih1_z}
    ulonglong2* wB = (ulonglong2*)(smc + W_B1);      // {Whh1_r, Whh1_z}
    ulonglong2* wC = (ulonglong2*)(smc + W_C1);      // {Wih1_n, Whh1_n}
    u64* hb = (u64*)(smc + SM_HB);                   // 4 bufs x 1024 u64
    float4* bias0 = (float4*)(smc + SM_BI0);
    float4* bias1 = (float4*)(smc + SM_BI1);

    int tid = threadIdx.x;
    int l = tid & 31;
    int w = tid >> 5;        // 0..15
    int jl = l >> 3, rg = l & 7;
    int jj = w * 4 + jl;

    // ---- stage weights (per (j,kp): distinct-lane layouts) ----
    for (int i = tid; i < 64 * 32; i += 512) {
        int j = i >> 5, kp = i & 31;
        wrz0[j * 33 + kp] = make_ulonglong2(
            pack2(Whh0[(size_t)j * 64 + 2 * kp], Whh0[(size_t)j * 64 + 2 * kp + 1]),
            pack2(Whh0[(size_t)(64 + j) * 64 + 2 * kp], Whh0[(size_t)(64 + j) * 64 + 2 * kp + 1]));
        wn0[j * 33 + kp] =
            pack2(Whh0[(size_t)(128 + j) * 64 + 2 * kp], Whh0[(size_t)(128 + j) * 64 + 2 * kp + 1]);
        wA[j * 33 + kp] = make_ulonglong2(
            pack2(Wih1[(size_t)j * 64 + 2 * kp], Wih1[(size_t)j * 64 + 2 * kp + 1]),
            pack2(Wih1[(size_t)(64 + j) * 64 + 2 * kp], Wih1[(size_t)(64 + j) * 64 + 2 * kp + 1]));
        wB[j * 33 + kp] = make_ulonglong2(
            pack2(Whh1[(size_t)j * 64 + 2 * kp], Whh1[(size_t)j * 64 + 2 * kp + 1]),
            pack2(Whh1[(size_t)(64 + j) * 64 + 2 * kp], Whh1[(size_t)(64 + j) * 64 + 2 * kp + 1]));
        wC[j * 33 + kp] = make_ulonglong2(
            pack2(Wih1[(size_t)(128 + j) * 64 + 2 * kp], Wih1[(size_t)(128 + j) * 64 + 2 * kp + 1]),
            pack2(Whh1[(size_t)(128 + j) * 64 + 2 * kp], Whh1[(size_t)(128 + j) * 64 + 2 * kp + 1]));
    }
    if (tid < 64) {
        bias0[tid] = make_float4(bhh0[tid], bhh0[64 + tid], bhh0[128 + tid], 0.f);
        bias1[tid] = make_float4(bih1[tid] + bhh1[tid], bih1[64 + tid] + bhh1[64 + tid],
                                 bih1[128 + tid], bhh1[128 + tid]);
    }
    for (int i = tid; i < 4096; i += 512) hb[i] = 0ull;
    __syncthreads();

    int blk = blockIdx.x;
    int rowbase = blk * 32;

    // gi(0): gcur[m*3+g] for lane's (jj, rows rg+8m)
    float gcur[12];
    {
        const float* gp = g_gi + ((size_t)(0 * NBLK + blk) * 64) * 96 + jj * 96;
#pragma unroll
        for (int m = 0; m < 4; m++)
#pragma unroll
            for (int g = 0; g < 3; g++)
                gcur[m * 3 + g] = gp[g * 32 + rg + 8 * m];
    }

    int p = 0;
    for (int t = 0; t <= TT; t++) {
        // ===== layer 0, step t =====
        if (t < TT) {
            u64 aR[4], aZ[4], aN[4];
#pragma unroll
            for (int m = 0; m < 4; m++) { aR[m] = aZ[m] = aN[m] = 0ull; }
            const ulonglong2* h0p = (const ulonglong2*)(hb + p * 1024);
#pragma unroll
            for (int kp = 0; kp < 32; kp++) {
                ulonglong2 hA = h0p[kp * 16 + rg * 2];
                ulonglong2 hB = h0p[kp * 16 + rg * 2 + 1];
                ulonglong2 wv = wrz0[jj * 33 + kp];
                u64 wn = wn0[jj * 33 + kp];
                aR[0] = ffma2(hA.x, wv.x, aR[0]); aZ[0] = ffma2(hA.x, wv.y, aZ[0]); aN[0] = ffma2(hA.x, wn, aN[0]);
                aR[1] = ffma2(hA.y, wv.x, aR[1]); aZ[1] = ffma2(hA.y, wv.y, aZ[1]); aN[1] = ffma2(hA.y, wn, aN[1]);
                aR[2] = ffma2(hB.x, wv.x, aR[2]); aZ[2] = ffma2(hB.x, wv.y, aZ[2]); aN[2] = ffma2(hB.x, wn, aN[2]);
                aR[3] = ffma2(hB.y, wv.x, aR[3]); aZ[3] = ffma2(hB.y, wv.y, aZ[3]); aN[3] = ffma2(hB.y, wn, aN[3]);
            }
            float* hnew = (float*)(hb + (p ^ 1) * 1024);
            const float* hold = (const float*)(hb + p * 1024);
            float4 bv = bias0[jj];
#pragma unroll
            for (int m = 0; m < 4; m++) {
                float rga = sigf(gcur[m * 3 + 0] + sumh(aR[m]) + bv.x);
                float zg = sigf(gcur[m * 3 + 1] + sumh(aZ[m]) + bv.y);
                float ng = tanhf_fast(gcur[m * 3 + 2] + rga * (sumh(aN[m]) + bv.z));
                int fi = (jj >> 1) * 64 + (rg * 4 + m) * 2 + (jj & 1);
                float ho = hold[fi];
                hnew[fi] = ng + zg * (ho - ng);
            }
        }
        // prefetch gi for t+1
        if (t + 1 < TT) {
            const float* gp = g_gi + ((size_t)((t + 1) * NBLK + blk) * 64) * 96 + jj * 96;
#pragma unroll
            for (int m = 0; m < 4; m++)
#pragma unroll
                for (int g = 0; g < 3; g++)
                    gcur[m * 3 + g] = gp[g * 32 + rg + 8 * m];
        }
        // ===== layer 1, step t-1: x = hb[p] (= ys0(t-1)), h1: hb[2+p] -> hb[2+p^1] =====
        if (t > 0) {
            u64 ar[4], az[4], ai[4], ah[4];
#pragma unroll
            for (int m = 0; m < 4; m++) { ar[m] = az[m] = ai[m] = ah[m] = 0ull; }
            const ulonglong2* x1p = (const ulonglong2*)(hb + p * 1024);
            const ulonglong2* h1p = (const ulonglong2*)(hb + (2 + p) * 1024);
#pragma unroll
            for (int kp = 0; kp < 32; kp++) {
                ulonglong2 xA = x1p[kp * 16 + rg * 2];
                ulonglong2 xB = x1p[kp * 16 + rg * 2 + 1];
                ulonglong2 hA = h1p[kp * 16 + rg * 2];
                ulonglong2 hB = h1p[kp * 16 + rg * 2 + 1];
                ulonglong2 wa = wA[jj * 33 + kp];
                ulonglong2 wb = wB[jj * 33 + kp];
                ulonglong2 wc = wC[jj * 33 + kp];
                ar[0] = ffma2(xA.x, wa.x, ar[0]); az[0] = ffma2(xA.x, wa.y, az[0]);
                ar[0] = ffma2(hA.x, wb.x, ar[0]); az[0] = ffma2(hA.x, wb.y, az[0]);
                ai[0] = ffma2(xA.x, wc.x, ai[0]); ah[0] = ffma2(hA.x, wc.y, ah[0]);
                ar[1] = ffma2(xA.y, wa.x, ar[1]); az[1] = ffma2(xA.y, wa.y, az[1]);
                ar[1] = ffma2(hA.y, wb.x, ar[1]); az[1] = ffma2(hA.y, wb.y, az[1]);
                ai[1] = ffma2(xA.y, wc.x, ai[1]); ah[1] = ffma2(hA.y, wc.y, ah[1]);
                ar[2] = ffma2(xB.x, wa.x, ar[2]); az[2] = ffma2(xB.x, wa.y, az[2]);
                ar[2] = ffma2(hB.x, wb.x, ar[2]); az[2] = ffma2(hB.x, wb.y, az[2]);
                ai[2] = ffma2(xB.x, wc.x, ai[2]); ah[2] = ffma2(hB.x, wc.y, ah[2]);
                ar[3] = ffma2(xB.y, wa.x, ar[3]); az[3] = ffma2(xB.y, wa.y, az[3]);
                ar[3] = ffma2(hB.y, wb.x, ar[3]); az[3] = ffma2(hB.y, wb.y, az[3]);
                ai[3] = ffma2(xB.y, wc.x, ai[3]); ah[3] = ffma2(hB.y, wc.y, ah[3]);
            }
            float* hnew = (float*)(hb + (2 + (p ^ 1)) * 1024);
            const float* hold = (const float*)(hb + (2 + p) * 1024);
            float4 bv = bias1[jj];
#pragma unroll
            for (int m = 0; m < 4; m++) {
                float rga = sigf(sumh(ar[m]) + bv.x);
                float zg = sigf(sumh(az[m]) + bv.y);
                float ng = tanhf_fast(sumh(ai[m]) + bv.z + rga * (sumh(ah[m]) + bv.w));
                int fi = (jj >> 1) * 64 + (rg * 4 + m) * 2 + (jj & 1);
                float ho = hold[fi];
                hnew[fi] = ng + zg * (ho - ng);
            }
        }
        __syncthreads();
        p ^= 1;
    }

    // ===== classifier =====
    {
        u64 acc[4];
#pragma unroll
        for (int m = 0; m < 4; m++) acc[m] = 0ull;
        const ulonglong2* h1p = (const ulonglong2*)(hb + (2 + p) * 1024);
#pragma unroll
        for (int kp = 0; kp < 32; kp++) {
            ulonglong2 hA = h1p[kp * 16 + rg * 2];
            ulonglong2 hB = h1p[kp * 16 + rg * 2 + 1];
            u64 wv = *(const u64*)(cW1 + (size_t)jj * 64 + 2 * kp);
            acc[0] = ffma2(hA.x, wv, acc[0]);
            acc[1] = ffma2(hA.y, wv, acc[1]);
            acc[2] = ffma2(hB.x, wv, acc[2]);
            acc[3] = ffma2(hB.y, wv, acc[3]);
        }
        float* hidb = (float*)(hb + (p ^ 1) * 1024);   // dead h0 buffer
        float cb = cb1[jj];
#pragma unroll
        for (int m = 0; m < 4; m++)
            hidb[(jj >> 1) * 64 + (rg * 4 + m) * 2 + (jj & 1)] = fmaxf(sumh(acc[m]) + cb, 0.f);
    }
    __syncthreads();
    if (w < 8) {
        u64 a = 0ull;
        const u64* hp = hb + (p ^ 1) * 1024;
#pragma unroll
        for (int kp = 0; kp < 32; kp++) {
            u64 wv = *(const u64*)(cW2 + w * 64 + 2 * kp);
            a = ffma2(hp[kp * 32 + (l & 7) * 4 + (l >> 3)], wv, a);
        }
        out[(rowbase + l) * 8 + w] = sumh(a) + cb2[w];
    }
}

// ---------------- launch ----------------
extern "C" void kernel_launch(void* const* d_in, const int* in_sizes, int n_in,
                              void* d_out, int out_size) {
    const float* obs  = (const float*)d_in[0];
    const int*   act  = (const int*)d_in[1];
    const float* pW   = (const float*)d_in[2];
    const float* pb   = (const float*)d_in[3];
    const float* lg   = (const float*)d_in[4];
    const float* lb   = (const float*)d_in[5];
    const float* Wih0 = (const float*)d_in[6];
    const float* Whh0 = (const float*)d_in[7];
    const float* bih0 = (const float*)d_in[8];
    const float* bhh0 = (const float*)d_in[9];
    const float* Wih1 = (const float*)d_in[10];
    const float* Whh1 = (const float*)d_in[11];
    const float* bih1 = (const float*)d_in[12];
    const float* bhh1 = (const float*)d_in[13];
    const float* cW1  = (const float*)d_in[14];
    const float* cb1  = (const float*)d_in[15];
    const float* cW2  = (const float*)d_in[16];
    const float* cb2  = (const float*)d_in[17];
    float* out = (float*)d_out;

    cudaFuncSetAttribute(k_feat, cudaFuncAttributeMaxDynamicSharedMemorySize, KF_SMEM);
    cudaFuncSetAttribute(k_gi0, cudaFuncAttributeMaxDynamicSharedMemorySize, GI_SMEM);
    cudaFuncSetAttribute(k_gru, cudaFuncAttributeMaxDynamicSharedMemorySize, SMEM_TOTAL);

    k_feat<<<512, 256, KF_SMEM>>>(obs, act, pW, pb, lg, lb);
    k_gi0<<<256, 512, GI_SMEM>>>(Wih0, bih0);
    k_gru<<<NBLK, 512, SMEM_TOTAL>>>(Whh0, bhh0,
                                     Wih1, Whh1, bih1, bhh1,
                                     cW1, cb1, cW2, cb2, out);
}

// round 16
// speedup vs baseline: 1.0105x; 1.0105x over previous
#include <cuda_runtime.h>
#include <cstdint>
#include <cstddef>

#define BB 4096
#define TT 32
#define AA 4
#define OBSD 115
#define HH 64
#define KK 8
#define ACTN 19
#define FEATN 23
#define INDIM 99
#define NBLK 128
typedef unsigned long long u64;

__device__ float g_xall[(size_t)TT * BB * HH];
__device__ float g_gi[(size_t)TT * NBLK * 64 * 96];
__device__ float2 g_ys[(size_t)TT * NBLK * 1024];   // [t][blk][kp][r]
__device__ int g_flag[TT * NBLK];

__device__ __forceinline__ u64 ffma2(u64 a, u64 b, u64 c) {
    u64 d;
    asm("fma.rn.f32x2 %0, %1, %2, %3;" : "=l"(d) : "l"(a), "l"(b), "l"(c));
    return d;
}
__device__ __forceinline__ u64 pack2(float lo, float hi) {
    u64 d;
    asm("mov.b64 %0, {%1, %2};" : "=l"(d) : "f"(lo), "f"(hi));
    return d;
}
__device__ __forceinline__ float sumh(u64 v) {
    return __uint_as_float((unsigned)(v & 0xffffffffull)) +
           __uint_as_float((unsigned)(v >> 32));
}
__device__ __forceinline__ float sigf(float x) { return __fdividef(1.f, 1.f + __expf(-x)); }
__device__ __forceinline__ float tanhf_fast(float x) {
    return __fdividef(2.f, 1.f + __expf(-2.f * x)) - 1.f;
}

// ---------------- kernel 1: features + proj + LN + ReLU (R6, 62.7us) ----------------
#define KF_PT 0
#define KF_PAR 25344
#define KF_FB (25344 + 768)
#define KF_AB (KF_FB + 25600)
#define KF_SMEM (KF_AB + 4096)

__global__ __launch_bounds__(256) void k_feat(const float* __restrict__ obs,
                                              const int* __restrict__ act,
                                              const float* __restrict__ pW,
                                              const float* __restrict__ pb,
                                              const float* __restrict__ lg,
                                              const float* __restrict__ lb) {
    extern __shared__ char smc[];
    float2* pTp = (float2*)(smc + KF_PT);
    float2* sbp = (float2*)(smc + KF_PAR);
    float2* sgp = sbp + 32;
    float2* sbtp = sbp + 64;
    float* fbuf = (float*)(smc + KF_FB);
    int* abuf = (int*)(smc + KF_AB);

    int tid = threadIdx.x;
    for (int i = tid; i < INDIM * 32; i += 256) {
        int f = i >> 5, hp = i & 31;
        pTp[i] = make_float2(pW[(2 * hp) * INDIM + f], pW[(2 * hp + 1) * INDIM + f]);
    }
    if (tid < 32) {
        sbp[tid] = make_float2(pb[2 * tid], pb[2 * tid + 1]);
        sgp[tid] = make_float2(lg[2 * tid], lg[2 * tid + 1]);
        sbtp[tid] = make_float2(lb[2 * tid], lb[2 * tid + 1]);
    }
    {
        int task = blockIdx.x * 256 + tid;
        int b = task >> 5, t = task & 31;
        const float* o = obs + (size_t)(b * TT + t) * AA * OBSD;
        float px[AA], py[AA];
#pragma unroll
        for (int a = 0; a < AA; a++) { px[a] = o[a * OBSD]; py[a] = o[a * OBSD + 1]; }
        float bx = o[88], by = o[89];
        float bvx = 0.f, bvy = 0.f;
        if (t > 0) { bvx = bx - o[88 - AA * OBSD]; bvy = by - o[89 - AA * OBSD]; }
        float cx = 0.25f * (px[0] + px[1] + px[2] + px[3]);
        float cy = 0.25f * (py[0] + py[1] + py[2] + py[3]);
        float sp = 0.f;
#pragma unroll
        for (int a = 0; a < AA; a++) {
            float dx = px[a] - cx, dy = py[a] - cy;
            sp += dx * dx + dy * dy;
        }
        float spread = sqrtf(0.25f * sp + 1e-6f);
        float* fb = fbuf + tid * 25;
        fb[0] = bx; fb[1] = by; fb[2] = bvx; fb[3] = bvy;
#pragma unroll
        for (int a = 0; a < AA; a++) { fb[4 + 2 * a] = px[a]; fb[5 + 2 * a] = py[a]; }
        fb[12] = cx; fb[13] = cy; fb[14] = spread;
#pragma unroll
        for (int i = 0; i < AA; i++) {
            float best = 3.4e38f; int bj = 0;
#pragma unroll
            for (int j = 0; j < AA; j++) {
                if (j == i) continue;
                float dx = px[i] - px[j], dy = py[i] - py[j];
                float d = dx * dx + dy * dy;
                if (d < best) { best = d; bj = j; }
            }
            fb[15 + 2 * i] = px[bj] - px[i];
            fb[16 + 2 * i] = py[bj] - py[i];
        }
        const int* ap = act + (b * TT + t) * AA;
#pragma unroll
        for (int a = 0; a < AA; a++) abuf[tid * 4 + a] = FEATN + a * ACTN + ap[a];
    }
    __syncthreads();

    int lane = tid & 31, w = tid >> 5;
    const u64* pTq = (const u64*)pTp;
    u64 bini = *(const u64*)&sbp[lane];
    for (int tt = 0; tt < 32; tt++) {
        int s = w * 32 + tt;
        const float* fb = fbuf + s * 25;
        u64 acc = bini;
#pragma unroll
        for (int f = 0; f < FEATN; f++) {
            float x = fb[f];
            acc = ffma2(pack2(x, x), pTq[f * 32 + lane], acc);
        }
        u64 one2 = pack2(1.f, 1.f);
#pragma unroll
        for (int a = 0; a < AA; a++)
            acc = ffma2(one2, pTq[abuf[s * 4 + a] * 32 + lane], acc);
        float a0 = __uint_as_float((unsigned)(acc & 0xffffffffull));
        float a1 = __uint_as_float((unsigned)(acc >> 32));
        float sm = a0 + a1;
#pragma unroll
        for (int off = 16; off; off >>= 1) sm += __shfl_xor_sync(0xffffffffu, sm, off);
        float mu = sm * (1.f / 64.f);
        float d0 = a0 - mu, d1 = a1 - mu;
        float v = d0 * d0 + d1 * d1;
#pragma unroll
        for (int off = 16; off; off >>= 1) v += __shfl_xor_sync(0xffffffffu, v, off);
        float sc = rsqrtf(v * (1.f / 64.f) + 1e-5f);
        float2 g = sgp[lane], bt = sbtp[lane];
        float y0 = fmaxf(fmaf(d0 * sc, g.x, bt.x), 0.f);
        float y1 = fmaxf(fmaf(d1 * sc, g.y, bt.y), 0.f);
        int task = blockIdx.x * 256 + s;
        int b = task >> 5, t = task & 31;
        *(float2*)(g_xall + ((size_t)t * BB + b) * HH + 2 * lane) = make_float2(y0, y1);
    }
}

// ---------------- kernel 2: layer-0 input-gate GEMM (R14 one-wave) + flag zero ----------------
#define GI_XS 65536
#define GI_SBI (65536 + 16896)
#define GI_SMEM (GI_SBI + 768)
__global__ __launch_bounds__(512, 2) void k_gi0(const float* __restrict__ Wih0,
                                                const float* __restrict__ bih0) {
    extern __shared__ char smc[];
    float2* wq = (float2*)smc;
    float2* xs = (float2*)(smc + GI_XS);
    float* sbi = (float*)(smc + GI_SBI);

    int tid = threadIdx.x;
    if (blockIdx.x == 0)
        for (int i = tid; i < TT * NBLK; i += 512) g_flag[i] = 0;
    for (int i = tid; i < 64 * 32 * 4; i += 512) {
        int j = i >> 7, kp = (i >> 2) & 31, m = i & 3;
        float2 v = make_float2(0.f, 0.f);
        if (m < 3) {
            const float* src = Wih0 + (size_t)(m * 64 + j) * 64 + 2 * kp;
            v.x = src[0]; v.y = src[1];
        }
        wq[i] = v;
    }
    if (tid < 192) sbi[tid] = bih0[tid];

    int r = tid & 31, w = tid >> 5, jbase = w * 4;
    int blk = blockIdx.x & 127, tchunk = blockIdx.x >> 7;
    int rowbase = blk * 32;
    int t0 = tchunk * 16;

    for (int i = tid; i < 1024; i += 512) {
        int rr = i >> 5, kp = i & 31;
        xs[kp * 33 + rr] =
            *((const float2*)(g_xall + ((size_t)t0 * BB + rowbase + rr) * HH) + kp);
    }
    __syncthreads();

    for (int tq = 0; tq < 16; tq++) {
        int t = t0 + tq;
        if (tq + 1 < 16) {
            for (int i = tid; i < 1024; i += 512) {
                int rr = i >> 5, kp = i & 31;
                xs[((tq + 1) & 1) * 1056 + kp * 33 + rr] =
                    *((const float2*)(g_xall + ((size_t)(t + 1) * BB + rowbase + rr) * HH) + kp);
            }
        }
        const float2* xsrc = xs + (tq & 1) * 1056;
        u64 acc[12];
#pragma unroll
        for (int i = 0; i < 12; i++) acc[i] = 0ull;
#pragma unroll
        for (int kp = 0; kp < 32; kp++) {
            u64 x2 = *(const u64*)&xsrc[kp * 33 + r];
#pragma unroll
            for (int j = 0; j < 4; j++) {
                const ulonglong2* wp = (const ulonglong2*)&wq[((jbase + j) * 32 + kp) * 4];
                ulonglong2 wa = wp[0];
                ulonglong2 wb = wp[1];
                acc[j * 3 + 0] = ffma2(x2, wa.x, acc[j * 3 + 0]);
                acc[j * 3 + 1] = ffma2(x2, wa.y, acc[j * 3 + 1]);
                acc[j * 3 + 2] = ffma2(x2, wb.x, acc[j * 3 + 2]);
            }
        }
        float* gout = g_gi + ((size_t)(t * NBLK + blk) * 64) * 96;
#pragma unroll
        for (int j = 0; j < 4; j++) {
            int jj = jbase + j;
#pragma unroll
            for (int m = 0; m < 3; m++)
                gout[jj * 96 + m * 32 + r] = sumh(acc[j * 3 + m]) + sbi[m * 64 + jj];
        }
        __syncthreads();
    }
}

// ========== kernel 3: producer/consumer split GRU ==========
// grid 256: blk<128 = layer-0 producer; blk>=128 = layer-1 consumer + classifier.
// Uniform dyn smem 114688 -> 2 CTAs/SM co-resident, 8 warps/SMSP.
#define GRU_SMEM 114688

__global__ __launch_bounds__(512, 2) void k_gru2(
    const float* __restrict__ Whh0, const float* __restrict__ bhh0,
    const float* __restrict__ Wih1, const float* __restrict__ Whh1,
    const float* __restrict__ bih1, const float* __restrict__ bhh1,
    const float* __restrict__ cW1, const float* __restrict__ cb1,
    const float* __restrict__ cW2, const float* __restrict__ cb2,
    float* __restrict__ out) {
    extern __shared__ char smc[];
    int tid = threadIdx.x;
    int r = tid & 31;
    int w = tid >> 5;      // 0..15
    int jbase = w * 4;

    if (blockIdx.x < NBLK) {
        // ================= PRODUCER: layer 0 =================
        float2* wb0 = (float2*)smc;                 // [j][kp][4] 65536
        float2* hb = (float2*)(smc + 65536);        // 2 x 1024 float2
        float4* bias0 = (float4*)(smc + 65536 + 16384);
        int blk = blockIdx.x, rowbase = blk * 32;
        (void)rowbase;

        for (int i = tid; i < 64 * 32 * 4; i += 512) {
            int j = i >> 7, kp = (i >> 2) & 31, m = i & 3;
            float2 v = make_float2(0.f, 0.f);
            if (m < 3) {
                const float* src = Whh0 + (size_t)(m * 64 + j) * 64 + 2 * kp;
                v.x = src[0]; v.y = src[1];
            }
            wb0[i] = v;
        }
        if (tid < 64)
            bias0[tid] = make_float4(bhh0[tid], bhh0[64 + tid], bhh0[128 + tid], 0.f);
        for (int i = tid; i < 2048; i += 512) hb[i] = make_float2(0.f, 0.f);
        __syncthreads();

        const float2* wl0 = wb0 + (size_t)jbase * 32 * 4;
        float gcur[12];
        {
            const float* gp = g_gi + ((size_t)(0 * NBLK + blk) * 64) * 96 + r;
#pragma unroll
            for (int j = 0; j < 4; j++)
#pragma unroll
                for (int m = 0; m < 3; m++)
                    gcur[j * 3 + m] = gp[(jbase + j) * 96 + m * 32];
        }

        int p = 0;
        for (int t = 0; t < TT; t++) {
            u64 aR[4], aZ[4], aN[4];
#pragma unroll
            for (int j = 0; j < 4; j++) { aR[j] = aZ[j] = aN[j] = 0ull; }
            const u64* h0p = (const u64*)(hb + p * 1024);
#pragma unroll
            for (int kp = 0; kp < 32; kp++) {
                u64 h2 = h0p[kp * 32 + r];
#pragma unroll
                for (int j = 0; j < 4; j++) {
                    const ulonglong2* wp = (const ulonglong2*)(wl0 + (size_t)((j * 32 + kp) * 4));
                    ulonglong2 wa = wp[0];
                    ulonglong2 wb = wp[1];
                    aR[j] = ffma2(h2, wa.x, aR[j]);
                    aZ[j] = ffma2(h2, wa.y, aZ[j]);
                    aN[j] = ffma2(h2, wb.x, aN[j]);
                }
            }
            // gi prefetch t+1
            float gnext[12];
            if (t + 1 < TT) {
                const float* gp = g_gi + ((size_t)((t + 1) * NBLK + blk) * 64) * 96 + r;
#pragma unroll
                for (int j = 0; j < 4; j++)
#pragma unroll
                    for (int m = 0; m < 3; m++)
                        gnext[j * 3 + m] = gp[(jbase + j) * 96 + m * 32];
            }
            float* hnew = (float*)(hb + (p ^ 1) * 1024);
            const float* hold = (const float*)(hb + p * 1024);
            float hv[4];
#pragma unroll
            for (int j = 0; j < 4; j++) {
                int jj = jbase + j;
                float4 bv = bias0[jj];
                float rg = sigf(gcur[j * 3 + 0] + sumh(aR[j]) + bv.x);
                float zg = sigf(gcur[j * 3 + 1] + sumh(aZ[j]) + bv.y);
                float ng = tanhf_fast(gcur[j * 3 + 2] + rg * (sumh(aN[j]) + bv.z));
                float ho = hold[(jj >> 1) * 64 + r * 2 + (jj & 1)];
                hv[j] = ng + zg * (ho - ng);
                hnew[(jj >> 1) * 64 + r * 2 + (jj & 1)] = hv[j];
            }
            // publish ys0(t)
            float2* yo = g_ys + (size_t)(t * NBLK + blk) * 1024;
            yo[(2 * w) * 32 + r] = make_float2(hv[0], hv[1]);
            yo[(2 * w + 1) * 32 + r] = make_float2(hv[2], hv[3]);
            __threadfence();
            __syncthreads();
            if (tid == 0) atomicExch(&g_flag[t * NBLK + blk], 1);
#pragma unroll
            for (int i = 0; i < 12; i++) gcur[i] = gnext[i];
            p ^= 1;
        }
    } else {
        // ================= CONSUMER: layer 1 + classifier =================
        float2* wb1 = (float2*)smc;                  // [j][kp][6] 98304
        float2* h1 = (float2*)(smc + 98304);         // [kp][r] 8192
        float2* xs = (float2*)(smc + 98304 + 8192);  // [kp][r] 8192
        int blk = blockIdx.x - NBLK, rowbase = blk * 32;

        for (int i = tid; i < 64 * 32 * 6; i += 512) {
            int m = i % 6;
            int kp = (i / 6) & 31;
            int j = i / 192;
            int g = (m >> 1) * 64 + j;
            const float* src = (m & 1) ? Whh1 : Wih1;
            wb1[i] = make_float2(src[g * 64 + 2 * kp], src[g * 64 + 2 * kp + 1]);
        }
        for (int i = tid; i < 1024; i += 512) h1[i] = make_float2(0.f, 0.f);
        float4 bv[4];
#pragma unroll
        for (int j = 0; j < 4; j++) {
            int jj = jbase + j;
            bv[j] = make_float4(bih1[jj] + bhh1[jj], bih1[64 + jj] + bhh1[64 + jj],
                                bih1[128 + jj], bhh1[128 + jj]);
        }
        __syncthreads();

        const float2* wl1 = wb1 + (size_t)jbase * 32 * 6;
        for (int t = 0; t < TT; t++) {
            if (tid == 0) {
                while (atomicAdd(&g_flag[t * NBLK + blk], 0) == 0) __nanosleep(64);
            }
            __syncthreads();   // flag observed
            {
                const float4* src = (const float4*)(g_ys + (size_t)(t * NBLK + blk) * 1024);
                float4* dst = (float4*)xs;
                dst[tid] = src[tid];   // 512 x 16B = 8KB
            }
            __syncthreads();   // xs staged
            u64 ar[4], az[4], ai[4], ah[4];
#pragma unroll
            for (int j = 0; j < 4; j++) { ar[j] = az[j] = ai[j] = ah[j] = 0ull; }
            const u64* x1p = (const u64*)xs;
            const u64* h1p = (const u64*)h1;
#pragma unroll
            for (int kp = 0; kp < 32; kp++) {
                u64 x2 = x1p[kp * 32 + r];
                u64 h2 = h1p[kp * 32 + r];
#pragma unroll
                for (int j = 0; j < 4; j++) {
                    const ulonglong2* wp = (const ulonglong2*)(wl1 + (size_t)((j * 32 + kp) * 6));
                    ulonglong2 wa = wp[0];
                    ulonglong2 wb = wp[1];
                    ulonglong2 wc = wp[2];
                    ar[j] = ffma2(x2, wa.x, ar[j]); ar[j] = ffma2(h2, wa.y, ar[j]);
                    az[j] = ffma2(x2, wb.x, az[j]); az[j] = ffma2(h2, wb.y, az[j]);
                    ai[j] = ffma2(x2, wc.x, ai[j]);
                    ah[j] = ffma2(h2, wc.y, ah[j]);
                }
            }
            __syncthreads();   // all h1 reads done
            float* hw = (float*)h1;
#pragma unroll
            for (int j = 0; j < 4; j++) {
                int jj = jbase + j;
                float rg = sigf(sumh(ar[j]) + bv[j].x);
                float zg = sigf(sumh(az[j]) + bv[j].y);
                float ng = tanhf_fast(sumh(ai[j]) + bv[j].z + rg * (sumh(ah[j]) + bv[j].w));
                int fi = (jj >> 1) * 64 + r * 2 + (jj & 1);
                float ho = hw[fi];
                hw[fi] = ng + zg * (ho - ng);
            }
            // next phase's first barrier orders these writes
        }
        __syncthreads();
        // classifier
        {
            u64 acc[4];
#pragma unroll
            for (int j = 0; j < 4; j++) acc[j] = 0ull;
            const u64* h1p = (const u64*)h1;
#pragma unroll
            for (int kp = 0; kp < 32; kp++) {
                u64 h2 = h1p[kp * 32 + r];
#pragma unroll
                for (int j = 0; j < 4; j++)
                    acc[j] = ffma2(h2, *(const u64*)(cW1 + (jbase + j) * 64 + 2 * kp), acc[j]);
            }
            float* hidb = (float*)xs;
#pragma unroll
            for (int j = 0; j < 4; j++) {
                int jj = jbase + j;
                hidb[(jj >> 1) * 64 + r * 2 + (jj & 1)] =
                    fmaxf(sumh(acc[j]) + cb1[jj], 0.f);
            }
        }
        __syncthreads();
        if (w < 8) {
            u64 a = 0ull;
            const u64* hp = (const u64*)xs;
#pragma unroll
            for (int kp = 0; kp < 32; kp++)
                a = ffma2(hp[kp * 32 + r], *(const u64*)(cW2 + w * 64 + 2 * kp), a);
            out[(rowbase + r) * 8 + w] = sumh(a) + cb2[w];
        }
    }
}

// ---------------- launch ----------------
extern "C" void kernel_launch(void* const* d_in, const int* in_sizes, int n_in,
                              void* d_out, int out_size) {
    const float* obs  = (const float*)d_in[0];
    const int*   act  = (const int*)d_in[1];
    const float* pW   = (const float*)d_in[2];
    const float* pb   = (const float*)d_in[3];
    const float* lg   = (const float*)d_in[4];
    const float* lb   = (const float*)d_in[5];
    const float* Wih0 = (const float*)d_in[6];
    const float* Whh0 = (const float*)d_in[7];
    const float* bih0 = (const float*)d_in[8];
    const float* bhh0 = (const float*)d_in[9];
    const float* Wih1 = (const float*)d_in[10];
    const float* Whh1 = (const float*)d_in[11];
    const float* bih1 = (const float*)d_in[12];
    const float* bhh1 = (const float*)d_in[13];
    const float* cW1  = (const float*)d_in[14];
    const float* cb1  = (const float*)d_in[15];
    const float* cW2  = (const float*)d_in[16];
    const float* cb2  = (const float*)d_in[17];
    float* out = (float*)d_out;

    cudaFuncSetAttribute(k_feat, cudaFuncAttributeMaxDynamicSharedMemorySize, KF_SMEM);
    cudaFuncSetAttribute(k_gi0, cudaFuncAttributeMaxDynamicSharedMemorySize, GI_SMEM);
    cudaFuncSetAttribute(k_gru2, cudaFuncAttributeMaxDynamicSharedMemorySize, GRU_SMEM);

    k_feat<<<512, 256, KF_SMEM>>>(obs, act, pW, pb, lg, lb);
    k_gi0<<<256, 512, GI_SMEM>>>(Wih0, bih0);
    k_gru2<<<2 * NBLK, 512, GRU_SMEM>>>(Whh0, bhh0,
                                        Wih1, Whh1, bih1, bhh1,
                                        cW1, cb1, cW2, cb2, out);
}

// round 17
// speedup vs baseline: 1.2269x; 1.2141x over previous
#include <cuda_runtime.h>
#include <cstdint>
#include <cstddef>

#define BB 4096
#define TT 32
#define AA 4
#define OBSD 115
#define HH 64
#define KK 8
#define ACTN 19
#define FEATN 23
#define INDIM 99
#define NBLK 128
typedef unsigned long long u64;

// layer-0 input gates (+bih0): [t][blk][j][gate][row], stride 96
__device__ float g_gi[(size_t)TT * NBLK * 64 * 96];

__device__ __forceinline__ u64 ffma2(u64 a, u64 b, u64 c) {
    u64 d;
    asm("fma.rn.f32x2 %0, %1, %2, %3;" : "=l"(d) : "l"(a), "l"(b), "l"(c));
    return d;
}
__device__ __forceinline__ u64 pack2(float lo, float hi) {
    u64 d;
    asm("mov.b64 %0, {%1, %2};" : "=l"(d) : "f"(lo), "f"(hi));
    return d;
}
__device__ __forceinline__ float sumh(u64 v) {
    return __uint_as_float((unsigned)(v & 0xffffffffull)) +
           __uint_as_float((unsigned)(v >> 32));
}
__device__ __forceinline__ float sigf(float x) { return __fdividef(1.f, 1.f + __expf(-x)); }
__device__ __forceinline__ float tanhf_fast(float x) {
    return __fdividef(2.f, 1.f + __expf(-2.f * x)) - 1.f;
}

// ============ kernel 1: features + proj + LN + ReLU + layer0-input GEMM ============
// R7 version VERBATIM (measured 196.5us). 512 blocks = (tchunk 0..3) x (128
// row-tiles), 256 threads. Warp-synchronous after staging: thread s does
// features for (r=s&31, tq=s>>5); warp w projects its 32 tasks (t=w) then runs
// the gi0 GEMM for t=w. No g_xall round-trip.
#define FG_PT 0                         // pTp: 99*32 float2 = 25344
#define FG_PAR 25344                    // sbp/sgp/sbtp: 768
#define FG_WQ 26112                     // wq: 64*32*4 float2 = 65536
#define FG_SBI 91648                    // bih0: 768
#define FG_FB 92416                     // fbuf: 256*25*4 = 25600
#define FG_AB 118016                    // abuf: 256*4*4 = 4096
#define FG_XS 122112                    // xs: 8 * (32*33) float2 = 67584
#define FG_SMEM 189696

__global__ __launch_bounds__(256, 1) void k_featgi(
    const float* __restrict__ obs, const int* __restrict__ act,
    const float* __restrict__ pW, const float* __restrict__ pb,
    const float* __restrict__ lg, const float* __restrict__ lb,
    const float* __restrict__ Wih0, const float* __restrict__ bih0) {
    extern __shared__ char smc[];
    float2* pTp = (float2*)(smc + FG_PT);
    float2* sbp = (float2*)(smc + FG_PAR);
    float2* sgp = sbp + 32;
    float2* sbtp = sbp + 64;
    float2* wq = (float2*)(smc + FG_WQ);      // [j][kp][4] float2 (r,z,n,pad)
    float* sbi = (float*)(smc + FG_SBI);
    float* fbuf = (float*)(smc + FG_FB);      // [s][25]
    int* abuf = (int*)(smc + FG_AB);          // [s][4]
    float2* xs = (float2*)(smc + FG_XS);      // [tq][kp*33 + r]

    int tid = threadIdx.x;
    int blkRow = blockIdx.x & 127;
    int tchunk = blockIdx.x >> 7;
    int rowbase = blkRow * 32;

    // ---- stage smem tables ----
    for (int i = tid; i < INDIM * 32; i += 256) {
        int f = i >> 5, hp = i & 31;
        pTp[i] = make_float2(pW[(2 * hp) * INDIM + f], pW[(2 * hp + 1) * INDIM + f]);
    }
    for (int i = tid; i < 64 * 32 * 4; i += 256) {
        int j = i >> 7, kp = (i >> 2) & 31, m = i & 3;
        float2 v = make_float2(0.f, 0.f);
        if (m < 3) {
            const float* src = Wih0 + (size_t)(m * 64 + j) * 64 + 2 * kp;
            v.x = src[0]; v.y = src[1];
        }
        wq[i] = v;
    }
    if (tid < 192) sbi[tid] = bih0[tid];
    if (tid < 32) {
        sbp[tid] = make_float2(pb[2 * tid], pb[2 * tid + 1]);
        sgp[tid] = make_float2(lg[2 * tid], lg[2 * tid + 1]);
        sbtp[tid] = make_float2(lb[2 * tid], lb[2 * tid + 1]);
    }

    // ---- phase 1: per-thread feature extraction (own slot) ----
    {
        int r = tid & 31, tq = tid >> 5;
        int b = rowbase + r, t = tchunk * 8 + tq;
        const float* o = obs + (size_t)(b * TT + t) * AA * OBSD;
        float px[AA], py[AA];
#pragma unroll
        for (int a = 0; a < AA; a++) { px[a] = o[a * OBSD]; py[a] = o[a * OBSD + 1]; }
        float bx = o[88], by = o[89];
        float bvx = 0.f, bvy = 0.f;
        if (t > 0) { bvx = bx - o[88 - AA * OBSD]; bvy = by - o[89 - AA * OBSD]; }
        float cx = 0.25f * (px[0] + px[1] + px[2] + px[3]);
        float cy = 0.25f * (py[0] + py[1] + py[2] + py[3]);
        float sp = 0.f;
#pragma unroll
        for (int a = 0; a < AA; a++) {
            float dx = px[a] - cx, dy = py[a] - cy;
            sp += dx * dx + dy * dy;
        }
        float spread = sqrtf(0.25f * sp + 1e-6f);
        float* fb = fbuf + tid * 25;
        fb[0] = bx; fb[1] = by; fb[2] = bvx; fb[3] = bvy;
#pragma unroll
        for (int a = 0; a < AA; a++) { fb[4 + 2 * a] = px[a]; fb[5 + 2 * a] = py[a]; }
        fb[12] = cx; fb[13] = cy; fb[14] = spread;
#pragma unroll
        for (int i = 0; i < AA; i++) {
            float best = 3.4e38f; int bj = 0;
#pragma unroll
            for (int j = 0; j < AA; j++) {
                if (j == i) continue;
                float dx = px[i] - px[j], dy = py[i] - py[j];
                float d = dx * dx + dy * dy;
                if (d < best) { best = d; bj = j; }
            }
            fb[15 + 2 * i] = px[bj] - px[i];
            fb[16 + 2 * i] = py[bj] - py[i];
        }
        const int* ap = act + (b * TT + t) * AA;
#pragma unroll
        for (int a = 0; a < AA; a++) abuf[tid * 4 + a] = FEATN + a * ACTN + ap[a];
    }
    __syncthreads();   // staging + fbuf visible

    int lane = tid & 31, w = tid >> 5;   // warp w owns timestep tq = w
    float2* xs_t = xs + w * (32 * 33);

    // ---- phase 2: projection + LN + ReLU for warp's 32 tasks ----
    {
        const u64* pTq = (const u64*)pTp;
        u64 bini = *(const u64*)&sbp[lane];
        u64 one2 = pack2(1.f, 1.f);
        for (int tt = 0; tt < 32; tt++) {
            int s = w * 32 + tt;
            const float* fb = fbuf + s * 25;
            u64 acc = bini;
#pragma unroll
            for (int f = 0; f < FEATN; f++) {
                float x = fb[f];
                acc = ffma2(pack2(x, x), pTq[f * 32 + lane], acc);
            }
#pragma unroll
            for (int a = 0; a < AA; a++)
                acc = ffma2(one2, pTq[abuf[s * 4 + a] * 32 + lane], acc);
            float a0 = __uint_as_float((unsigned)(acc & 0xffffffffull));
            float a1 = __uint_as_float((unsigned)(acc >> 32));
            float sm = a0 + a1;
#pragma unroll
            for (int off = 16; off; off >>= 1) sm += __shfl_xor_sync(0xffffffffu, sm, off);
            float mu = sm * (1.f / 64.f);
            float d0 = a0 - mu, d1 = a1 - mu;
            float v = d0 * d0 + d1 * d1;
#pragma unroll
            for (int off = 16; off; off >>= 1) v += __shfl_xor_sync(0xffffffffu, v, off);
            float sc = rsqrtf(v * (1.f / 64.f) + 1e-5f);
            float2 g = sgp[lane], bt = sbtp[lane];
            float y0 = fmaxf(fmaf(d0 * sc, g.x, bt.x), 0.f);
            float y1 = fmaxf(fmaf(d1 * sc, g.y, bt.y), 0.f);
            xs_t[lane * 33 + tt] = make_float2(y0, y1);   // [kp][r]
        }
    }
    __syncwarp();

    // ---- phase 3: gi0 GEMM for t = tchunk*8 + w (lane = row) ----
    {
        int t = tchunk * 8 + w;
        int r = lane;
        float* gout = g_gi + ((size_t)(t * NBLK + blkRow) * 64) * 96;
#pragma unroll 1
        for (int jg = 0; jg < 8; jg++) {
            int jb = jg * 8;
            u64 acc[24];
#pragma unroll
            for (int i = 0; i < 24; i++) acc[i] = 0ull;
#pragma unroll
            for (int kp = 0; kp < 32; kp++) {
                u64 x2 = *(const u64*)&xs_t[kp * 33 + r];
#pragma unroll
                for (int j = 0; j < 8; j++) {
                    const ulonglong2* wp = (const ulonglong2*)&wq[((jb + j) * 32 + kp) * 4];
                    ulonglong2 wa = wp[0];
                    ulonglong2 wb = wp[1];
                    acc[j * 3 + 0] = ffma2(x2, wa.x, acc[j * 3 + 0]);
                    acc[j * 3 + 1] = ffma2(x2, wa.y, acc[j * 3 + 1]);
                    acc[j * 3 + 2] = ffma2(x2, wb.x, acc[j * 3 + 2]);
                }
            }
#pragma unroll
            for (int j = 0; j < 8; j++) {
                int jj = jb + j;
#pragma unroll
                for (int m = 0; m < 3; m++)
                    gout[jj * 96 + m * 32 + r] = sumh(acc[j * 3 + m]) + sbi[m * 64 + jj];
            }
        }
    }
}

// ========== kernel 2: fused 2-layer GRU recurrence + classifier ==========
// R6 512-thread version VERBATIM (measured-best 386us): 16 warps, 4 j per warp,
// ONE barrier per phase (layer0 t and layer1 t-1 both read only p-buffers).
// smem: wb0 65536 | wb1 98304 | hb 32768 | bias0 1024 | bias1 1024 = 198656
#define SM_WB1 65536
#define SM_HB (65536 + 98304)
#define SM_B0 (SM_HB + 32768)
#define SM_B1 (SM_B0 + 1024)
#define SMEM_TOTAL (SM_B1 + 1024)

__global__ __launch_bounds__(512, 1) void k_gru(
    const float* __restrict__ Whh0, const float* __restrict__ bhh0,
    const float* __restrict__ Wih1, const float* __restrict__ Whh1,
    const float* __restrict__ bih1, const float* __restrict__ bhh1,
    const float* __restrict__ cW1, const float* __restrict__ cb1,
    const float* __restrict__ cW2, const float* __restrict__ cb2,
    float* __restrict__ out) {
    extern __shared__ char smc[];
    float2* wb0 = (float2*)smc;              // [j][kp][4] float2: Whh0 r,z,n,pad
    float2* wb1 = (float2*)(smc + SM_WB1);   // [j][kp][6] float2
    float2* hb = (float2*)(smc + SM_HB);     // 4 buffers of [kp][r] float2
    float4* bias0 = (float4*)(smc + SM_B0);
    float4* bias1 = (float4*)(smc + SM_B1);

    int tid = threadIdx.x;
    int r = tid & 31;
    int w = tid >> 5;        // 0..15
    int jbase = w * 4;       // 4 hidden dims per warp

    // ---- stage weights ----
    for (int i = tid; i < 64 * 32 * 4; i += 512) {
        int j = i >> 7, kp = (i >> 2) & 31, m = i & 3;
        float2 v = make_float2(0.f, 0.f);
        if (m < 3) {
            const float* src = Whh0 + (size_t)(m * 64 + j) * 64 + 2 * kp;
            v.x = src[0]; v.y = src[1];
        }
        wb0[i] = v;
    }
    for (int i = tid; i < 64 * 32 * 6; i += 512) {
        int m = i % 6;
        int kp = (i / 6) & 31;
        int j = i / 192;
        int g = (m >> 1) * 64 + j;
        const float* src = (m & 1) ? Whh1 : Wih1;
        float2 v;
        v.x = src[g * 64 + 2 * kp];
        v.y = src[g * 64 + 2 * kp + 1];
        wb1[i] = v;
    }
    if (tid < 64) {
        bias0[tid] = make_float4(bhh0[tid], bhh0[64 + tid], bhh0[128 + tid], 0.f);
        bias1[tid] = make_float4(bih1[tid] + bhh1[tid], bih1[64 + tid] + bhh1[64 + tid],
                                 bih1[128 + tid], bhh1[128 + tid]);
    }
    for (int i = tid; i < 4 * 1024; i += 512) hb[i] = make_float2(0.f, 0.f);
    __syncthreads();

    int blk = blockIdx.x;
    int rowbase = blk * 32;
    const float2* wl0 = wb0 + (size_t)jbase * 32 * 4;
    const float2* wl1 = wb1 + (size_t)jbase * 32 * 6;

    // prefetch gi for t=0
    float gcur[12];
    {
        const float* gp = g_gi + ((size_t)(0 * NBLK + blk) * 64) * 96 + r;
#pragma unroll
        for (int j = 0; j < 4; j++)
#pragma unroll
            for (int m = 0; m < 3; m++)
                gcur[j * 3 + m] = gp[(jbase + j) * 96 + m * 32];
    }

    int p = 0;
    for (int t = 0; t <= TT; t++) {
        // ===== layer 0, step t: h0[p] -> h0[p^1] =====
        if (t < TT) {
            u64 aR[4], aZ[4], aN[4];
#pragma unroll
            for (int j = 0; j < 4; j++) { aR[j] = aZ[j] = aN[j] = 0ull; }
            const u64* h0p = (const u64*)(hb + p * 1024);
#pragma unroll
            for (int kp = 0; kp < 32; kp++) {
                u64 h2 = h0p[kp * 32 + r];
#pragma unroll
                for (int j = 0; j < 4; j++) {
                    const ulonglong2* wp = (const ulonglong2*)(wl0 + (size_t)((j * 32 + kp) * 4));
                    ulonglong2 wa = wp[0];
                    ulonglong2 wb = wp[1];
                    aR[j] = ffma2(h2, wa.x, aR[j]);
                    aZ[j] = ffma2(h2, wa.y, aZ[j]);
                    aN[j] = ffma2(h2, wb.x, aN[j]);
                }
            }
            float* hnew = (float*)(hb + (p ^ 1) * 1024);
            const float* hold = (const float*)(hb + p * 1024);
#pragma unroll
            for (int j = 0; j < 4; j++) {
                int jj = jbase + j;
                float4 bv = bias0[jj];
                float rg = sigf(gcur[j * 3 + 0] + sumh(aR[j]) + bv.x);
                float zg = sigf(gcur[j * 3 + 1] + sumh(aZ[j]) + bv.y);
                float ng = tanhf_fast(gcur[j * 3 + 2] + rg * (sumh(aN[j]) + bv.z));
                float ho = hold[(jj >> 1) * 64 + r * 2 + (jj & 1)];
                hnew[(jj >> 1) * 64 + r * 2 + (jj & 1)] = ng + zg * (ho - ng);
            }
        }
        // prefetch gi for t+1 (hidden under layer-1 compute)
        if (t + 1 < TT) {
            const float* gp = g_gi + ((size_t)((t + 1) * NBLK + blk) * 64) * 96 + r;
#pragma unroll
            for (int j = 0; j < 4; j++)
#pragma unroll
                for (int m = 0; m < 3; m++)
                    gcur[j * 3 + m] = gp[(jbase + j) * 96 + m * 32];
        }
        // ===== layer 1, step t-1: x = h0[p] (= ys0[t-1]), h1[p] -> h1[p^1] =====
        if (t > 0) {
            u64 ar[4], az[4], ai[4], ah[4];
#pragma unroll
            for (int j = 0; j < 4; j++) { ar[j] = az[j] = ai[j] = ah[j] = 0ull; }
            const u64* x1p = (const u64*)(hb + p * 1024);
            const u64* h1p = (const u64*)(hb + (2 + p) * 1024);
#pragma unroll
            for (int kp = 0; kp < 32; kp++) {
                u64 x2 = x1p[kp * 32 + r];
                u64 h2 = h1p[kp * 32 + r];
#pragma unroll
                for (int j = 0; j < 4; j++) {
                    const ulonglong2* wp = (const ulonglong2*)(wl1 + (size_t)((j * 32 + kp) * 6));
                    ulonglong2 wa = wp[0];
                    ulonglong2 wb = wp[1];
                    ulonglong2 wc = wp[2];
                    ar[j] = ffma2(x2, wa.x, ar[j]); ar[j] = ffma2(h2, wa.y, ar[j]);
                    az[j] = ffma2(x2, wb.x, az[j]); az[j] = ffma2(h2, wb.y, az[j]);
                    ai[j] = ffma2(x2, wc.x, ai[j]);
                    ah[j] = ffma2(h2, wc.y, ah[j]);
                }
            }
            float* hnew = (float*)(hb + (2 + (p ^ 1)) * 1024);
            const float* hold = (const float*)(hb + (2 + p) * 1024);
#pragma unroll
            for (int j = 0; j < 4; j++) {
                int jj = jbase + j;
                float4 bv = bias1[jj];
                float rg = sigf(sumh(ar[j]) + bv.x);
                float zg = sigf(sumh(az[j]) + bv.y);
                float ng = tanhf_fast(sumh(ai[j]) + bv.z + rg * (sumh(ah[j]) + bv.w));
                float ho = hold[(jj >> 1) * 64 + r * 2 + (jj & 1)];
                hnew[(jj >> 1) * 64 + r * 2 + (jj & 1)] = ng + zg * (ho - ng);
            }
        }
        __syncthreads();
        p ^= 1;
    }

    // ===== classifier: hid = relu(h1 @ cls_W1.T + b1) ; logits = hid @ cls_W2.T + b2 =====
    {
        u64 acc[4];
#pragma unroll
        for (int j = 0; j < 4; j++) acc[j] = 0ull;
        const u64* h1p = (const u64*)(hb + (2 + p) * 1024);
#pragma unroll
        for (int kp = 0; kp < 32; kp++) {
            u64 h2 = h1p[kp * 32 + r];
#pragma unroll
            for (int j = 0; j < 4; j++)
                acc[j] = ffma2(h2, *(const u64*)(cW1 + (jbase + j) * 64 + 2 * kp), acc[j]);
        }
        float* hidb = (float*)(hb + (p ^ 1) * 1024);   // dead h0 buffer
#pragma unroll
        for (int j = 0; j < 4; j++) {
            int jj = jbase + j;
            float hv = fmaxf(sumh(acc[j]) + cb1[jj], 0.f);
            hidb[(jj >> 1) * 64 + r * 2 + (jj & 1)] = hv;
        }
    }
    __syncthreads();
    if (w < 8) {
        u64 a = 0ull;
        const u64* hp = (const u64*)(hb + (p ^ 1) * 1024);
#pragma unroll
        for (int kp = 0; kp < 32; kp++)
            a = ffma2(hp[kp * 32 + r], *(const u64*)(cW2 + w * 64 + 2 * kp), a);
        out[(rowbase + r) * 8 + w] = sumh(a) + cb2[w];
    }
}

// ---------------- launch ----------------
extern "C" void kernel_launch(void* const* d_in, const int* in_sizes, int n_in,
                              void* d_out, int out_size) {
    const float* obs  = (const float*)d_in[0];
    const int*   act  = (const int*)d_in[1];
    const float* pW   = (const float*)d_in[2];
    const float* pb   = (const float*)d_in[3];
    const float* lg   = (const float*)d_in[4];
    const float* lb   = (const float*)d_in[5];
    const float* Wih0 = (const float*)d_in[6];
    const float* Whh0 = (const float*)d_in[7];
    const float* bih0 = (const float*)d_in[8];
    const float* bhh0 = (const float*)d_in[9];
    const float* Wih1 = (const float*)d_in[10];
    const float* Whh1 = (const float*)d_in[11];
    const float* bih1 = (const float*)d_in[12];
    const float* bhh1 = (const float*)d_in[13];
    const float* cW1  = (const float*)d_in[14];
    const float* cb1  = (const float*)d_in[15];
    const float* cW2  = (const float*)d_in[16];
    const float* cb2  = (const float*)d_in[17];
    float* out = (float*)d_out;

    cudaFuncSetAttribute(k_featgi, cudaFuncAttributeMaxDynamicSharedMemorySize, FG_SMEM);
    cudaFuncSetAttribute(k_gru, cudaFuncAttributeMaxDynamicSharedMemorySize, SMEM_TOTAL);

    k_featgi<<<512, 256, FG_SMEM>>>(obs, act, pW, pb, lg, lb, Wih0, bih0);
    k_gru<<<NBLK, 512, SMEM_TOTAL>>>(Whh0, bhh0,
                                     Wih1, Whh1, bih1, bhh1,
                                     cW1, cb1, cW2, cb2, out);
}